// round 3
// baseline (speedup 1.0000x reference)
#include <cuda_runtime.h>
#include <cstdint>
#include <cmath>
#include <complex>
#include <cstring>

// ---------------------------------------------------------------------------
// Problem constants (fixed by setup_inputs)
//   b=2, n_src=4096, n_tgt=2048, p=32, C=32, NUM_SH=16, S=3
//   signal channels Ct = 512, y tile = 48 x 512 per target
// ---------------------------------------------------------------------------
#define NTGT_TOTAL 4096          // b * n_tgt
#define YS 512                   // y row stride (floats)
#define NZC 3300                 // dense CG coef slots (exact total 3269)
#define NTASK_CAP 40
#define NCOPY_CAP 32

struct CopyD { int yoff; int addr; int tstride; };
struct TaskD { int yoff; int addr; int tstride; int nch;
               int coef; int j21; int l21; int J21; int z0; int z1; };
struct Plan {
    CopyD copies[NCOPY_CAP];
    TaskD tasks[NTASK_CAP];
    unsigned long long coef[NZC];   // duplicated {c,c} f32x2 pairs, [x][y][z]
    int ncopy, ntasks;
};

// ---- packed f32x2 helpers (Blackwell sm_100+) ------------------------------
__device__ __forceinline__ unsigned long long pack2(float lo, float hi) {
    unsigned long long r;
    asm("mov.b64 %0, {%1, %2};" : "=l"(r) : "f"(lo), "f"(hi));
    return r;
}
__device__ __forceinline__ void unpack2(unsigned long long v, float& lo, float& hi) {
    asm("mov.b64 {%0, %1}, %2;" : "=f"(lo), "=f"(hi) : "l"(v));
}
__device__ __forceinline__ void fma2(unsigned long long& d,
                                     unsigned long long a, unsigned long long b) {
    asm("fma.rn.f32x2 %0, %1, %2, %0;" : "+l"(d) : "l"(a), "l"(b));
}

// ---------------------------------------------------------------------------
// Kernel: one CTA (512 thr) per target point.
//  Phase 0: gather patches (32x512) + K tile + CG coef table into smem
//  Phase 1: y[48][512] = K^T @ patches, packed-f32x2 register tile
//  Phase 2: blocked CG epilogue: warp = (j,l,J[,z-range]) task, row-cached
// ---------------------------------------------------------------------------
__global__ __launch_bounds__(512, 1)
void sh_conv_kernel(const float* __restrict__ f0, const float* __restrict__ f1,
                    const float* __restrict__ f2, const float* __restrict__ f3,
                    const float* __restrict__ Kg, const int* __restrict__ pidx,
                    float* __restrict__ out, const __grid_constant__ Plan plan)
{
    extern __shared__ float sm[];
    float* ybuf = sm;                  // 48*512 floats; rows 0..31 alias patch tile
    float* Ks   = sm + 48 * YS;        // 32*48 floats
    unsigned long long* coefS =
        reinterpret_cast<unsigned long long*>(sm + 48 * YS + 1536);  // NZC u64
    __shared__ int idxS[32];

    const int tid = threadIdx.x;
    const int t   = blockIdx.x;        // t = b*2048 + v
    const int b   = t >> 11;

    // ---- load K tile + patch indices + stage coef table into smem ----
    {
        const float4* Kg4 = reinterpret_cast<const float4*>(Kg) + (size_t)t * 384;
        float4* Ks4 = reinterpret_cast<float4*>(Ks);
        if (tid < 384) Ks4[tid] = Kg4[tid];
        if (tid < 32)  idxS[tid] = pidx[t * 32 + tid];
        #pragma unroll
        for (int i = tid; i < NZC; i += 512) coefS[i] = plan.coef[i];
    }
    __syncthreads();

    // ---- gather patches into ybuf[p][c] (32 rows x 512 cols) ----
    {
        const int bbase = b << 12;     // b * 4096
        #pragma unroll
        for (int it = tid; it < 4096; it += 512) {
            const int p  = it >> 7;
            const int cc = it & 127;
            const int c  = cc << 2;
            const float* srcp; int rs, lo;
            if      (c < 32)  { srcp = f0; rs = 32;  lo = 0;   }
            else if (c < 128) { srcp = f1; rs = 96;  lo = 32;  }
            else if (c < 288) { srcp = f2; rs = 160; lo = 128; }
            else              { srcp = f3; rs = 224; lo = 288; }
            const float4 v = *reinterpret_cast<const float4*>(
                srcp + (size_t)(bbase + idxS[p]) * rs + (c - lo));
            *reinterpret_cast<float4*>(ybuf + (p << 9) + c) = v;
        }
    }
    __syncthreads();

    // ---- phase 1: GEMM. thread = (rowgroup rg of 12 rows) x (colgroup cg of 4 cols)
    const int rg = tid >> 7;           // 0..3
    const int cg = tid & 127;          // 0..127
    const int r0 = rg * 12;
    const int c0 = cg << 2;

    unsigned long long acc2[24];
    #pragma unroll
    for (int i = 0; i < 24; i++) acc2[i] = 0ull;

    #pragma unroll 4
    for (int p = 0; p < 32; p++) {
        const float4 v = *reinterpret_cast<const float4*>(ybuf + (p << 9) + c0);
        unsigned long long vb[4];
        vb[0] = pack2(v.x, v.x); vb[1] = pack2(v.y, v.y);
        vb[2] = pack2(v.z, v.z); vb[3] = pack2(v.w, v.w);
        const ulonglong2* kp = reinterpret_cast<const ulonglong2*>(Ks + p * 48 + r0);
        const ulonglong2 k01 = kp[0];
        const ulonglong2 k23 = kp[1];
        const ulonglong2 k45 = kp[2];
        const unsigned long long kpair[6] =
            {k01.x, k01.y, k23.x, k23.y, k45.x, k45.y};
        #pragma unroll
        for (int jj = 0; jj < 6; jj++) {
            fma2(acc2[jj * 4 + 0], kpair[jj], vb[0]);
            fma2(acc2[jj * 4 + 1], kpair[jj], vb[1]);
            fma2(acc2[jj * 4 + 2], kpair[jj], vb[2]);
            fma2(acc2[jj * 4 + 3], kpair[jj], vb[3]);
        }
    }
    __syncthreads();                   // everyone done reading patch rows

    #pragma unroll
    for (int jj = 0; jj < 6; jj++) {
        float4 we, wo;
        unpack2(acc2[jj * 4 + 0], we.x, wo.x);
        unpack2(acc2[jj * 4 + 1], we.y, wo.y);
        unpack2(acc2[jj * 4 + 2], we.z, wo.z);
        unpack2(acc2[jj * 4 + 3], we.w, wo.w);
        *reinterpret_cast<float4*>(ybuf + (r0 + 2 * jj)     * YS + c0) = we;
        *reinterpret_cast<float4*>(ybuf + (r0 + 2 * jj + 1) * YS + c0) = wo;
    }
    __syncthreads();

    // ---- phase 2: blocked CG epilogue. warp = task, 24 active lanes ----
    const int warp = tid >> 5;
    const int lane = tid & 31;
    if (lane < 24) {
        const int s    = lane >> 3;            // 0..2
        const int cq   = (lane & 7) << 2;      // 0,4,...,28
        const int peroff = s * YS + cq;
        const int uoff   = (s << 5) + cq;

        // identity copies (l=0 and j=0 paths)
        for (int ci = warp; ci < plan.ncopy; ci += 16) {
            const CopyD cd = plan.copies[ci];
            const float4 v = *reinterpret_cast<const float4*>(ybuf + cd.yoff + peroff);
            *reinterpret_cast<float4*>(out + (size_t)cd.addr +
                                       (size_t)t * cd.tstride + uoff) = v;
        }
        // CG tasks: row-cached dense contraction
        for (int ti = warp; ti < plan.ntasks; ti += 16) {
            const TaskD tk = plan.tasks[ti];
            const int nz = tk.z1 - tk.z0;
            const int lJ = tk.l21 * tk.J21;
            unsigned long long aA[7], aB[7];
            #pragma unroll
            for (int i = 0; i < 7; i++) { aA[i] = 0ull; aB[i] = 0ull; }

            for (int x = 0; x < tk.j21; x++) {
                const float* yb = ybuf + tk.yoff + x * (3 * YS) + peroff;
                const unsigned long long* cp = coefS + tk.coef + x * lJ + tk.z0;
                unsigned long long rA[7], rB[7];
                #pragma unroll
                for (int y = 0; y < 7; y++) if (y < tk.l21) {
                    const ulonglong2 v =
                        *reinterpret_cast<const ulonglong2*>(yb + y * 32);
                    rA[y] = v.x; rB[y] = v.y;
                }
                #pragma unroll
                for (int y = 0; y < 7; y++) if (y < tk.l21) {
                    const unsigned long long* cpy = cp + y * tk.J21;
                    #pragma unroll
                    for (int zi = 0; zi < 7; zi++) if (zi < nz) {
                        const unsigned long long c2 = cpy[zi];
                        fma2(aA[zi], c2, rA[y]);
                        fma2(aB[zi], c2, rB[y]);
                    }
                }
            }
            float* ob = out + (size_t)tk.addr + (size_t)t * tk.tstride + uoff;
            #pragma unroll
            for (int zi = 0; zi < 7; zi++) if (zi < nz) {
                float4 o;
                unpack2(aA[zi], o.x, o.y);
                unpack2(aB[zi], o.z, o.w);
                *reinterpret_cast<float4*>(ob + (tk.z0 + zi) * tk.nch) = o;
            }
        }
    }
}

// ---------------------------------------------------------------------------
// Host: Clebsch-Gordan tables (Racah formula + real-basis change), plan build.
// Recomputed every call (deterministic, no caching), passed as kernel param.
// ---------------------------------------------------------------------------
namespace shplan {

typedef std::complex<double> cd;

static double dfact(int n) { double r = 1.0; for (int i = 2; i <= n; i++) r *= i; return r; }

static double su2cg(int j1, int m1, int j2, int m2, int j3, int m3)
{
    if (m3 != m1 + m2) return 0.0;
    int vmin = -j1 + j2 + m3;
    if (-j1 + m1 > vmin) vmin = -j1 + m1;
    if (0 > vmin) vmin = 0;
    int vmax = j2 + j3 + m1;
    if (j3 - j1 + j2 < vmax) vmax = j3 - j1 + j2;
    if (j3 + m3 < vmax) vmax = j3 + m3;
    const double c = std::sqrt(
        (2.0 * j3 + 1.0) * dfact(j3 + j1 - j2) * dfact(j3 - j1 + j2) *
        dfact(j1 + j2 - j3) / dfact(j1 + j2 + j3 + 1) *
        dfact(j3 + m3) * dfact(j3 - m3) /
        (dfact(j1 - m1) * dfact(j1 + m1) * dfact(j2 - m2) * dfact(j2 + m2)));
    double s = 0.0;
    for (int v = vmin; v <= vmax; v++) {
        double term = dfact(j2 + j3 + m1 - v) * dfact(j1 - m1 + v) /
                      (dfact(v) * dfact(j3 - j1 + j2 - v) *
                       dfact(j3 + m3 - v) * dfact(v + j1 - j2 - m3));
        if ((v + j2 + m2) & 1) term = -term;
        s += term;
    }
    return c * s;
}

static void r2c(int l, cd q[7][7])
{
    for (int i = 0; i < 7; i++)
        for (int j = 0; j < 7; j++) q[i][j] = cd(0.0, 0.0);
    const double is2 = 1.0 / std::sqrt(2.0);
    for (int m = -l; m < 0; m++) {
        q[l + m][l - m] = cd(is2, 0.0);
        q[l + m][l + m] = cd(0.0, -is2);
    }
    q[l][l] = cd(1.0, 0.0);
    for (int m = 1; m <= l; m++) {
        const double sg = (m & 1) ? -1.0 : 1.0;
        q[l + m][l + m] = cd(sg * is2, 0.0);
        q[l + m][l - m] = cd(0.0, sg * is2);
    }
    cd ph;
    switch (l & 3) {
        case 0: ph = cd(1, 0);  break;
        case 1: ph = cd(0, -1); break;
        case 2: ph = cd(-1, 0); break;
        default: ph = cd(0, 1); break;
    }
    const int n = 2 * l + 1;
    for (int i = 0; i < n; i++)
        for (int j = 0; j < n; j++) q[i][j] *= ph;
}

static void realcg(int j, int l, int J, double C[7][7][7])
{
    cd qj[7][7], ql[7][7], qJ[7][7];
    r2c(j, qj); r2c(l, ql); r2c(J, qJ);
    for (int a = 0; a < 2 * j + 1; a++)
        for (int bb = 0; bb < 2 * l + 1; bb++)
            for (int n = 0; n < 2 * J + 1; n++) {
                cd s(0.0, 0.0);
                for (int i = 0; i < 2 * j + 1; i++)
                    for (int k = 0; k < 2 * l + 1; k++)
                        for (int m = 0; m < 2 * J + 1; m++) {
                            const double cg = su2cg(j, i - j, l, k - l, J, m - J);
                            if (cg == 0.0) continue;
                            s += qj[i][a] * ql[k][bb] * std::conj(qJ[m][n]) * cg;
                        }
                C[a][bb][n] = s.real();
            }
}

static unsigned long long dup2(float c)
{
    unsigned int u; std::memcpy(&u, &c, 4);
    return (unsigned long long)u | ((unsigned long long)u << 32);
}

static void build_plan(Plan& P)
{
    // out0: (2,2048,1,384)  out1: (2,2048,3,864)
    // out2: (2,2048,5,1056) out3: (2,2048,7,960)
    const int base[4] = {0, 1572864, 12189696, 33816576};
    const int nch[4]  = {384, 864, 1056, 960};
    int tstr[4];
    for (int J = 0; J < 4; J++) tstr[J] = (2 * J + 1) * nch[J];

    const int sh0[4]  = {0, 1, 4, 9};       // sh offset for degree-j block
    const int offl[4] = {0, 32, 128, 288};  // channel offset for degree-l block

    int chpos[4] = {0, 0, 0, 0};
    int ncopy = 0, ntask = 0, nzc = 0;

    // l=0 copies (one per J): out_z = y[(sh0_J + z)*3 + s][c]
    for (int J = 0; J < 4; J++) {
        for (int z = 0; z < 2 * J + 1; z++) {
            P.copies[ncopy].yoff = (sh0[J] + z) * 3 * YS;
            P.copies[ncopy].addr = base[J] + z * nch[J] + chpos[J];
            P.copies[ncopy].tstride = tstr[J];
            ncopy++;
        }
        chpos[J] += 96;
    }
    // j=0 copies (one per l>=1): out_z = y[s][off_l + z*32 + c]
    for (int L = 1; L < 4; L++) {
        for (int z = 0; z < 2 * L + 1; z++) {
            P.copies[ncopy].yoff = offl[L] + z * 32;
            P.copies[ncopy].addr = base[L] + z * nch[L] + chpos[L];
            P.copies[ncopy].tstride = tstr[L];
            ncopy++;
        }
        chpos[L] += 96;
    }
    // CG paths, in cg_terms order: l outer (1..3), j inner (1..3), J ascending
    static double C[7][7][7];
    for (int l = 1; l < 4; l++)
        for (int j = 1; j < 4; j++) {
            const int Jmin = (j > l) ? (j - l) : (l - j);
            const int Jmax = (j + l > 3) ? 3 : (j + l);
            for (int J = Jmin; J <= Jmax; J++) {
                realcg(j, l, J, C);
                const int j21 = 2 * j + 1, l21 = 2 * l + 1, J21 = 2 * J + 1;
                const int coff = nzc;
                for (int x = 0; x < j21; x++)
                    for (int y = 0; y < l21; y++)
                        for (int z = 0; z < J21; z++)
                            P.coef[nzc++] = dup2((float)C[x][y][z]);
                const int cost = j21 * l21 * J21;
                const int nsplit = (cost > 200) ? 2 : 1;
                const int half = (J21 + 1) / 2;
                for (int sidx = 0; sidx < nsplit; sidx++) {
                    TaskD& tk = P.tasks[ntask++];
                    tk.yoff = sh0[j] * 3 * YS + offl[l];
                    tk.addr = base[J] + chpos[J];
                    tk.tstride = tstr[J];
                    tk.nch = nch[J];
                    tk.coef = coff;
                    tk.j21 = j21; tk.l21 = l21; tk.J21 = J21;
                    if (nsplit == 1) { tk.z0 = 0; tk.z1 = J21; }
                    else if (sidx == 0) { tk.z0 = 0; tk.z1 = half; }
                    else { tk.z0 = half; tk.z1 = J21; }
                }
                chpos[J] += 96;
            }
        }
    // pad coef
    for (int i = nzc; i < NZC; i++) P.coef[i] = 0ull;
    // sort tasks by descending cost for warp balance (insertion sort)
    for (int i = 1; i < ntask; i++) {
        TaskD key = P.tasks[i];
        const int kc = key.j21 * key.l21 * (key.z1 - key.z0);
        int k2 = i - 1;
        while (k2 >= 0 &&
               P.tasks[k2].j21 * P.tasks[k2].l21 *
                   (P.tasks[k2].z1 - P.tasks[k2].z0) < kc) {
            P.tasks[k2 + 1] = P.tasks[k2];
            k2--;
        }
        P.tasks[k2 + 1] = key;
    }
    // pad unused task/copy slots deterministically
    for (int i = ntask; i < NTASK_CAP; i++) {
        P.tasks[i] = TaskD{0, 0, 0, 0, 0, 0, 0, 1, 0, 0};
    }
    for (int i = ncopy; i < NCOPY_CAP; i++) P.copies[i] = CopyD{0, 0, 0};
    P.ncopy = ncopy;
    P.ntasks = ntask;
}

} // namespace shplan

// ---------------------------------------------------------------------------
extern "C" void kernel_launch(void* const* d_in, const int* in_sizes, int n_in,
                              void* d_out, int out_size)
{
    const float* f0  = (const float*)d_in[0];
    const float* f1  = (const float*)d_in[1];
    const float* f2  = (const float*)d_in[2];
    const float* f3  = (const float*)d_in[3];
    const float* Kg  = (const float*)d_in[4];
    const int* pidx  = (const int*)d_in[5];
    float* out = (float*)d_out;

    Plan plan;                      // ~28 KB on host stack
    shplan::build_plan(plan);

    const int smem_bytes = (48 * YS + 1536) * sizeof(float) + NZC * 8;  // 130848
    cudaFuncSetAttribute(sh_conv_kernel,
                         cudaFuncAttributeMaxDynamicSharedMemorySize, smem_bytes);

    sh_conv_kernel<<<NTGT_TOTAL, 512, smem_bytes>>>(f0, f1, f2, f3, Kg, pidx, out, plan);
}

// round 6
// speedup vs baseline: 2.8086x; 2.8086x over previous
#include <cuda_runtime.h>
#include <cstdint>
#include <cmath>
#include <complex>
#include <cstring>

// ---------------------------------------------------------------------------
// Problem constants (fixed by setup_inputs)
//   b=2, n_src=4096, n_tgt=2048, p=32, C=32, NUM_SH=16, S=3
//   signal channels Ct = 512, y tile = 48 x 512 per target
// ---------------------------------------------------------------------------
#define NTGT_TOTAL 4096          // b * n_tgt
#define YS 512                   // y row stride (floats)
#define NROWS 156                // total output rows across all 4 output arrays
#define NZCAP 3400               // >= max CG nonzeros

struct RowD { int addr; int tstride; int start; int cnt; };
struct NZT  { int off; float c; };
struct Plan { RowD rows[NROWS]; NZT nz[NZCAP]; };

// ---- packed f32x2 helpers (Blackwell sm_100+) ------------------------------
__device__ __forceinline__ unsigned long long pack2(float lo, float hi) {
    unsigned long long r;
    asm("mov.b64 %0, {%1, %2};" : "=l"(r) : "f"(lo), "f"(hi));
    return r;
}
__device__ __forceinline__ void unpack2(unsigned long long v, float& lo, float& hi) {
    asm("mov.b64 {%0, %1}, %2;" : "=f"(lo), "=f"(hi) : "l"(v));
}
__device__ __forceinline__ void fma2(unsigned long long& d,
                                     unsigned long long a, unsigned long long b) {
    asm("fma.rn.f32x2 %0, %1, %2, %0;" : "+l"(d) : "l"(a), "l"(b));
}

// ---------------------------------------------------------------------------
// Kernel: one CTA (1024 thr, 32 warps) per target point.
//  Phase 0: gather patches (32x512) + K tile (32x48) into smem
//  Phase 1: y[48][512] = K^T @ patches; thread = 12 rows x 2 cols, f32x2
//  Phase 2: sparse CG epilogue (per-output-row, warp-stride 32)
// ---------------------------------------------------------------------------
__global__ __launch_bounds__(1024, 1)
void sh_conv_kernel(const float* __restrict__ f0, const float* __restrict__ f1,
                    const float* __restrict__ f2, const float* __restrict__ f3,
                    const float* __restrict__ Kg, const int* __restrict__ pidx,
                    float* __restrict__ out, const __grid_constant__ Plan plan)
{
    extern __shared__ float sm[];
    float* ybuf = sm;                  // 48*512 floats; rows 0..31 alias patch tile
    float* Ks   = sm + 48 * YS;        // 32*48 floats
    __shared__ int idxS[32];

    const int tid = threadIdx.x;
    const int t   = blockIdx.x;        // t = b*2048 + v
    const int b   = t >> 11;

    // ---- load K tile (1536 floats) + patch indices ----
    {
        const float4* Kg4 = reinterpret_cast<const float4*>(Kg) + (size_t)t * 384;
        float4* Ks4 = reinterpret_cast<float4*>(Ks);
        if (tid < 384) Ks4[tid] = Kg4[tid];
        if (tid < 32)  idxS[tid] = pidx[t * 32 + tid];
    }
    __syncthreads();

    // ---- gather patches into ybuf[p][c] (32 rows x 512 cols) ----
    {
        const int bbase = b << 12;     // b * 4096
        #pragma unroll
        for (int it = tid; it < 4096; it += 1024) {
            const int p  = it >> 7;
            const int cc = it & 127;
            const int c  = cc << 2;
            const float* srcp; int rs, lo;
            if      (c < 32)  { srcp = f0; rs = 32;  lo = 0;   }
            else if (c < 128) { srcp = f1; rs = 96;  lo = 32;  }
            else if (c < 288) { srcp = f2; rs = 160; lo = 128; }
            else              { srcp = f3; rs = 224; lo = 288; }
            const float4 v = *reinterpret_cast<const float4*>(
                srcp + (size_t)(bbase + idxS[p]) * rs + (c - lo));
            *reinterpret_cast<float4*>(ybuf + (p << 9) + c) = v;
        }
    }
    __syncthreads();

    // ---- phase 1: GEMM. thread = 12 rows x 2 cols.
    //      rg = tid>>8 (4 rowgroups of 12 rows), cg = tid&255 (256 colgroups of 2)
    const int rg = tid >> 8;
    const int cg = tid & 255;
    const int r0 = rg * 12;
    const int c0 = cg << 1;

    unsigned long long acc2[12];       // [rowpair jj][col 0..1], pair={row2jj,row2jj+1}
    #pragma unroll
    for (int i = 0; i < 12; i++) acc2[i] = 0ull;

    #pragma unroll 4
    for (int p = 0; p < 32; p++) {
        const float2 v = *reinterpret_cast<const float2*>(ybuf + (p << 9) + c0);
        const unsigned long long vb0 = pack2(v.x, v.x);
        const unsigned long long vb1 = pack2(v.y, v.y);
        // K row pairs straight out of 128-bit smem loads (broadcast, no packs)
        const ulonglong2* kp = reinterpret_cast<const ulonglong2*>(Ks + p * 48 + r0);
        const ulonglong2 k01 = kp[0];
        const ulonglong2 k23 = kp[1];
        const ulonglong2 k45 = kp[2];
        const unsigned long long kpair[6] =
            {k01.x, k01.y, k23.x, k23.y, k45.x, k45.y};
        #pragma unroll
        for (int jj = 0; jj < 6; jj++) {
            fma2(acc2[jj * 2 + 0], kpair[jj], vb0);
            fma2(acc2[jj * 2 + 1], kpair[jj], vb1);
        }
    }
    __syncthreads();                   // everyone done reading patch rows

    #pragma unroll
    for (int jj = 0; jj < 6; jj++) {
        float e0, o0, e1, o1;
        unpack2(acc2[jj * 2 + 0], e0, o0);   // col c0:   rows 2jj, 2jj+1
        unpack2(acc2[jj * 2 + 1], e1, o1);   // col c0+1: rows 2jj, 2jj+1
        float2 we; we.x = e0; we.y = e1;
        float2 wo; wo.x = o0; wo.y = o1;
        *reinterpret_cast<float2*>(ybuf + (r0 + 2 * jj)     * YS + c0) = we;
        *reinterpret_cast<float2*>(ybuf + (r0 + 2 * jj + 1) * YS + c0) = wo;
    }
    __syncthreads();

    // ---- phase 2: CG epilogue. warp -> output row; 24 active lanes (3 s x 8 float4)
    const int warp = tid >> 5;
    const int lane = tid & 31;
    if (lane < 24) {
        const int s    = lane >> 3;            // 0..2
        const int cLoc = (lane & 7) << 2;      // 0,4,...,28
        const int peroff = s * YS + cLoc;      // y offset for this lane
        const int uoff   = (s << 5) + cLoc;    // output channel offset within 96
        for (int row = warp; row < NROWS; row += 32) {
            const RowD rd = plan.rows[row];
            float ax = 0.f, ay = 0.f, az = 0.f, aw = 0.f;
            int e = rd.start;
            for (int n = 0; n < rd.cnt; n++, e++) {
                const NZT z = plan.nz[e];
                const float4 v = *reinterpret_cast<const float4*>(ybuf + z.off + peroff);
                ax = fmaf(z.c, v.x, ax);
                ay = fmaf(z.c, v.y, ay);
                az = fmaf(z.c, v.z, az);
                aw = fmaf(z.c, v.w, aw);
            }
            float4 o; o.x = ax; o.y = ay; o.z = az; o.w = aw;
            *reinterpret_cast<float4*>(out + (size_t)rd.addr +
                                       (size_t)t * rd.tstride + uoff) = o;
        }
    }
}

// ---------------------------------------------------------------------------
// Host: Clebsch-Gordan tables (Racah formula + real-basis change), plan build.
// Recomputed every call (deterministic, no caching), passed as kernel param.
// ---------------------------------------------------------------------------
namespace shplan {

typedef std::complex<double> cd;

static double dfact(int n) { double r = 1.0; for (int i = 2; i <= n; i++) r *= i; return r; }

static double su2cg(int j1, int m1, int j2, int m2, int j3, int m3)
{
    if (m3 != m1 + m2) return 0.0;
    int vmin = -j1 + j2 + m3;
    if (-j1 + m1 > vmin) vmin = -j1 + m1;
    if (0 > vmin) vmin = 0;
    int vmax = j2 + j3 + m1;
    if (j3 - j1 + j2 < vmax) vmax = j3 - j1 + j2;
    if (j3 + m3 < vmax) vmax = j3 + m3;
    const double c = std::sqrt(
        (2.0 * j3 + 1.0) * dfact(j3 + j1 - j2) * dfact(j3 - j1 + j2) *
        dfact(j1 + j2 - j3) / dfact(j1 + j2 + j3 + 1) *
        dfact(j3 + m3) * dfact(j3 - m3) /
        (dfact(j1 - m1) * dfact(j1 + m1) * dfact(j2 - m2) * dfact(j2 + m2)));
    double s = 0.0;
    for (int v = vmin; v <= vmax; v++) {
        double term = dfact(j2 + j3 + m1 - v) * dfact(j1 - m1 + v) /
                      (dfact(v) * dfact(j3 - j1 + j2 - v) *
                       dfact(j3 + m3 - v) * dfact(v + j1 - j2 - m3));
        if ((v + j2 + m2) & 1) term = -term;
        s += term;
    }
    return c * s;
}

// real->complex change-of-basis matrix, scaled by (-i)^l
static void r2c(int l, cd q[7][7])
{
    for (int i = 0; i < 7; i++)
        for (int j = 0; j < 7; j++) q[i][j] = cd(0.0, 0.0);
    const double is2 = 1.0 / std::sqrt(2.0);
    for (int m = -l; m < 0; m++) {
        q[l + m][l - m] = cd(is2, 0.0);
        q[l + m][l + m] = cd(0.0, -is2);
    }
    q[l][l] = cd(1.0, 0.0);
    for (int m = 1; m <= l; m++) {
        const double sg = (m & 1) ? -1.0 : 1.0;
        q[l + m][l + m] = cd(sg * is2, 0.0);
        q[l + m][l - m] = cd(0.0, sg * is2);
    }
    cd ph;
    switch (l & 3) {
        case 0: ph = cd(1, 0);  break;
        case 1: ph = cd(0, -1); break;
        case 2: ph = cd(-1, 0); break;
        default: ph = cd(0, 1); break;
    }
    const int n = 2 * l + 1;
    for (int i = 0; i < n; i++)
        for (int j = 0; j < n; j++) q[i][j] *= ph;
}

// real-basis CG tensor C[x][y][z], sizes (2j+1, 2l+1, 2J+1)
static void realcg(int j, int l, int J, double C[7][7][7])
{
    cd qj[7][7], ql[7][7], qJ[7][7];
    r2c(j, qj); r2c(l, ql); r2c(J, qJ);
    for (int a = 0; a < 2 * j + 1; a++)
        for (int bb = 0; bb < 2 * l + 1; bb++)
            for (int n = 0; n < 2 * J + 1; n++) {
                cd s(0.0, 0.0);
                for (int i = 0; i < 2 * j + 1; i++)
                    for (int k = 0; k < 2 * l + 1; k++)
                        for (int m = 0; m < 2 * J + 1; m++) {
                            const double cg = su2cg(j, i - j, l, k - l, J, m - J);
                            if (cg == 0.0) continue;
                            s += qj[i][a] * ql[k][bb] * std::conj(qJ[m][n]) * cg;
                        }
                C[a][bb][n] = s.real();
            }
}

static void build_plan(Plan& P)
{
    // out0: (2,2048,1,384)  out1: (2,2048,3,864)
    // out2: (2,2048,5,1056) out3: (2,2048,7,960)
    const int base[4] = {0, 1572864, 12189696, 33816576};
    const int nch[4]  = {384, 864, 1056, 960};
    int tstr[4];
    for (int J = 0; J < 4; J++) tstr[J] = (2 * J + 1) * nch[J];

    const int sh0[4]  = {0, 1, 4, 9};       // sh offset for degree-j block
    const int offl[4] = {0, 32, 128, 288};  // channel offset for degree-l block

    int chpos[4] = {0, 0, 0, 0};
    int nrow = 0, nnz = 0;

    // l=0 copies (one per J): out_z = y[(sh0_J + z)*3 + s][c]
    for (int J = 0; J < 4; J++) {
        for (int z = 0; z < 2 * J + 1; z++) {
            P.nz[nnz].off = (sh0[J] + z) * 3 * YS;
            P.nz[nnz].c = 1.0f;
            P.rows[nrow].addr = base[J] + z * nch[J] + chpos[J];
            P.rows[nrow].tstride = tstr[J];
            P.rows[nrow].start = nnz;
            P.rows[nrow].cnt = 1;
            nrow++; nnz++;
        }
        chpos[J] += 96;
    }
    // j=0 copies (one per l>=1): out_z = y[s][off_l + z*32 + c]
    for (int L = 1; L < 4; L++) {
        for (int z = 0; z < 2 * L + 1; z++) {
            P.nz[nnz].off = offl[L] + z * 32;
            P.nz[nnz].c = 1.0f;
            P.rows[nrow].addr = base[L] + z * nch[L] + chpos[L];
            P.rows[nrow].tstride = tstr[L];
            P.rows[nrow].start = nnz;
            P.rows[nrow].cnt = 1;
            nrow++; nnz++;
        }
        chpos[L] += 96;
    }
    // CG paths, in cg_terms order: l outer (1..3), j inner (1..3), J ascending
    static double C[7][7][7];
    for (int l = 1; l < 4; l++)
        for (int j = 1; j < 4; j++) {
            const int Jmin = (j > l) ? (j - l) : (l - j);
            const int Jmax = (j + l > 3) ? 3 : (j + l);
            for (int J = Jmin; J <= Jmax; J++) {
                realcg(j, l, J, C);
                for (int z = 0; z < 2 * J + 1; z++) {
                    const int st = nnz;
                    for (int x = 0; x < 2 * j + 1; x++)
                        for (int y = 0; y < 2 * l + 1; y++) {
                            const double v = C[x][y][z];
                            if (std::fabs(v) > 1e-12 && nnz < NZCAP) {
                                P.nz[nnz].off = (sh0[j] + x) * 3 * YS + offl[l] + y * 32;
                                P.nz[nnz].c = (float)v;
                                nnz++;
                            }
                        }
                    P.rows[nrow].addr = base[J] + z * nch[J] + chpos[J];
                    P.rows[nrow].tstride = tstr[J];
                    P.rows[nrow].start = st;
                    P.rows[nrow].cnt = nnz - st;
                    nrow++;
                }
                chpos[J] += 96;
            }
        }
    // pad any unused nz slots deterministically
    for (int i = nnz; i < NZCAP; i++) { P.nz[i].off = 0; P.nz[i].c = 0.0f; }
}

} // namespace shplan

// ---------------------------------------------------------------------------
extern "C" void kernel_launch(void* const* d_in, const int* in_sizes, int n_in,
                              void* d_out, int out_size)
{
    const float* f0  = (const float*)d_in[0];
    const float* f1  = (const float*)d_in[1];
    const float* f2  = (const float*)d_in[2];
    const float* f3  = (const float*)d_in[3];
    const float* Kg  = (const float*)d_in[4];
    const int* pidx  = (const int*)d_in[5];
    float* out = (float*)d_out;

    Plan plan;                      // ~30 KB on host stack
    shplan::build_plan(plan);

    const int smem_bytes = (48 * YS + 32 * 48) * sizeof(float);  // 104448
    cudaFuncSetAttribute(sh_conv_kernel,
                         cudaFuncAttributeMaxDynamicSharedMemorySize, smem_bytes);

    sh_conv_kernel<<<NTGT_TOTAL, 1024, smem_bytes>>>(f0, f1, f2, f3, Kg, pidx, out, plan);
}